// round 6
// baseline (speedup 1.0000x reference)
#include <cuda_runtime.h>

// IntentGCN fused kernel v4: one block per (n,t) slice, 4x4 register tiles,
// 3 blocks/SM (reg-capped + smem diet), xoT overlaid on qnT, parallel softmax.
// N=32, C_IN=C_OUT=64, K=3, T=300, V=25, H=4, DK=DV=16.

#define VP 28    // padded v (stride for [*][v] arrays)
#define VB_S 68  // stride for [v][64] arrays

// shared memory float offsets (76,096 bytes total)
#define OF_FAT  0        // faT[64][28]
#define OF_QNT  1792     // qnT[64][28]  -- overlaid by xoT after S3
#define OF_XOT  1792     // xoT[64][28]  (written S6, read S7)
#define OF_QT   3584     // qT[64][28]
#define OF_KT   5376     // kT[64][28]
#define OF_VB   7168     // vB[25][68]
#define OF_SC   8868     // scT[4][25][28]  (h stride 700)
#define OF_G    11668    // g[75][64]
#define OF_A    16468    // A[75][28]
#define OF_MISC 18568    // 6*64 + 32 + 32 + pad
#define SMEM_FLOATS 19024
#define SMEM_BYTES (SMEM_FLOATS * 4)

// One conv-branch output tile (low-register form: scalar weight loads).
// g[k][v0..v0+3][co0..co0+3] = fa @ conv_w[k]^T + bias
__device__ __forceinline__ void conv_tile(int tt, const float* __restrict__ sFAT,
                                          const float* __restrict__ convw,
                                          const float* __restrict__ convb,
                                          float* __restrict__ sG)
{
    int k = tt / 112, r = tt % 112;
    int vg = r % 7, cog = r / 7;
    int v0 = vg * 4, co0 = cog * 4;
    const float* wb0 = convw + (k*64 + co0 + 0) * 64;
    const float* wb1 = convw + (k*64 + co0 + 1) * 64;
    const float* wb2 = convw + (k*64 + co0 + 2) * 64;
    const float* wb3 = convw + (k*64 + co0 + 3) * 64;
    float acc[4][4];
    #pragma unroll
    for (int coi = 0; coi < 4; coi++) {
        float bv = convb[k*64 + co0 + coi];
        #pragma unroll
        for (int vi = 0; vi < 4; vi++) acc[vi][coi] = bv;
    }
    #pragma unroll 4
    for (int ci = 0; ci < 64; ci++) {
        float4 la = *reinterpret_cast<const float4*>(sFAT + ci*VP + v0);
        float w0 = wb0[ci], w1 = wb1[ci], w2 = wb2[ci], w3 = wb3[ci];
        acc[0][0] += la.x*w0; acc[0][1] += la.x*w1; acc[0][2] += la.x*w2; acc[0][3] += la.x*w3;
        acc[1][0] += la.y*w0; acc[1][1] += la.y*w1; acc[1][2] += la.y*w2; acc[1][3] += la.y*w3;
        acc[2][0] += la.z*w0; acc[2][1] += la.z*w1; acc[2][2] += la.z*w2; acc[2][3] += la.z*w3;
        acc[3][0] += la.w*w0; acc[3][1] += la.w*w1; acc[3][2] += la.w*w2; acc[3][3] += la.w*w3;
    }
    #pragma unroll
    for (int vi = 0; vi < 4; vi++) {
        if (v0 + vi < 25) {
            float4 o; o.x = acc[vi][0]; o.y = acc[vi][1]; o.z = acc[vi][2]; o.w = acc[vi][3];
            *reinterpret_cast<float4*>(sG + (k*25 + v0 + vi)*64 + co0) = o;
        }
    }
}

__global__ __launch_bounds__(512, 3)
void intentgcn_kernel(
    const float* __restrict__ x,    const float* __restrict__ Ag,
    const float* __restrict__ bn1g, const float* __restrict__ bn1b,
    const float* __restrict__ bn1m, const float* __restrict__ bn1v,
    const float* __restrict__ convw, const float* __restrict__ convb,
    const float* __restrict__ lng,  const float* __restrict__ lnb,
    const float* __restrict__ wq,   const float* __restrict__ wk,
    const float* __restrict__ wv,   const float* __restrict__ fcw,
    const float* __restrict__ gatep,
    const float* __restrict__ bn2g, const float* __restrict__ bn2b,
    const float* __restrict__ bn2m, const float* __restrict__ bn2v,
    float* __restrict__ out)
{
    extern __shared__ float sm[];
    float* sFAT = sm + OF_FAT;
    float* sQNT = sm + OF_QNT;
    float* sQT  = sm + OF_QT;
    float* sKT  = sm + OF_KT;
    float* sVB  = sm + OF_VB;
    float* sSC  = sm + OF_SC;
    float* sXOT = sm + OF_XOT;   // overlays sQNT
    float* sG   = sm + OF_G;
    float* sA   = sm + OF_A;
    float* sB1S = sm + OF_MISC;
    float* sB1B = sB1S + 64;
    float* sB2S = sB1B + 64;
    float* sB2B = sB2S + 64;
    float* sLNg = sB2B + 64;
    float* sLNb = sLNg + 64;
    float* sMU  = sLNb + 64;   // 32
    float* sRS  = sMU + 32;    // 32
    float* sGate = sRS + 32;

    const int tid = threadIdx.x;
    const int t = blockIdx.x;
    const int n = blockIdx.y;

    // ---------------- S0: params, A, pad-zeroing, bn1 ----------------
    if (tid < 64) {
        float s1 = bn1g[tid] * rsqrtf(bn1v[tid] + 1e-5f);
        sB1S[tid] = s1;
        sB1B[tid] = bn1b[tid] - bn1m[tid] * s1;
        float s2 = bn2g[tid] * rsqrtf(bn2v[tid] + 1e-5f);
        sB2S[tid] = s2;
        sB2B[tid] = bn2b[tid] - bn2m[tid] * s2;
        sLNg[tid] = lng[tid];
        sLNb[tid] = lnb[tid];
    }
    if (tid == 0) sGate[0] = gatep[0];
    for (int i = tid; i < 192; i += 512) {           // zero padded v-cols
        int c = i / 3, vp = 25 + i % 3;
        sFAT[c*VP + vp] = 0.f;
        sQNT[c*VP + vp] = 0.f;
    }
    for (int i = tid; i < 225; i += 512)             // zero padded A w-cols
        sA[(i/3)*VP + 25 + i % 3] = 0.f;
    for (int i = tid; i < 1875; i += 512) {          // A[75][25] -> stride 28
        int kv = i / 25, w = i - kv*25;
        sA[kv*VP + w] = Ag[i];
    }
    __syncthreads();   // sB1S/B ready before use below

    const float* xb = x + (size_t)(n*64*300 + t) * 25;
    for (int i = tid; i < 1600; i += 512) {
        int c = i / 25, v = i - c*25;
        sFAT[c*VP + v] = xb[c*7500 + v] * sB1S[c] + sB1B[c];
    }
    __syncthreads();

    // ---------------- S1: per-token LayerNorm stats (shfl tree) ----------------
    if (tid < 256) {
        int v = tid >> 3;
        int j = tid & 7;
        int vv = (v < 25) ? v : 24;
        float s = 0.f, s2 = 0.f;
        #pragma unroll
        for (int cc = 0; cc < 8; cc++) {
            float xv = sFAT[(j*8 + cc)*VP + vv];
            s += xv; s2 += xv*xv;
        }
        s  += __shfl_down_sync(0xFFFFFFFFu, s, 4);
        s2 += __shfl_down_sync(0xFFFFFFFFu, s2, 4);
        s  += __shfl_down_sync(0xFFFFFFFFu, s, 2);
        s2 += __shfl_down_sync(0xFFFFFFFFu, s2, 2);
        s  += __shfl_down_sync(0xFFFFFFFFu, s, 1);
        s2 += __shfl_down_sync(0xFFFFFFFFu, s2, 1);
        if (j == 0 && v < 25) {
            float mu = s * (1.f/64.f);
            float var = s2 * (1.f/64.f) - mu*mu;
            sMU[v] = mu;
            sRS[v] = rsqrtf(var + 1e-6f);
        }
    }
    __syncthreads();

    // ---------------- S2: qn (transposed) ----------------
    for (int i = tid; i < 1600; i += 512) {
        int c = i / 25, v = i - c*25;
        sQNT[c*VP + v] = (sFAT[c*VP + v] - sMU[v]) * sRS[v] * sLNg[c] + sLNb[c];
    }
    __syncthreads();

    // ---------------- S3: q/k/v projections (336 thr) || conv tiles 0..175 ----
    if (tid < 336) {
        int m = tid / 112, r = tid % 112;
        int vg = r % 7, dg = r / 7;
        int v0 = vg * 4, d0 = dg * 4;
        const float* src = (m == 0) ? sQNT : sFAT;
        const float* wsel = (m == 0) ? wq : ((m == 1) ? wk : wv);
        float acc[4][4];
        #pragma unroll
        for (int i = 0; i < 4; i++)
            #pragma unroll
            for (int j = 0; j < 4; j++) acc[i][j] = 0.f;
        #pragma unroll 4
        for (int c = 0; c < 64; c++) {
            float4 a4 = *reinterpret_cast<const float4*>(src + c*VP + v0);
            float4 b4 = *reinterpret_cast<const float4*>(wsel + c*64 + d0);
            acc[0][0] += b4.x*a4.x; acc[0][1] += b4.x*a4.y; acc[0][2] += b4.x*a4.z; acc[0][3] += b4.x*a4.w;
            acc[1][0] += b4.y*a4.x; acc[1][1] += b4.y*a4.y; acc[1][2] += b4.y*a4.z; acc[1][3] += b4.y*a4.w;
            acc[2][0] += b4.z*a4.x; acc[2][1] += b4.z*a4.y; acc[2][2] += b4.z*a4.z; acc[2][3] += b4.z*a4.w;
            acc[3][0] += b4.w*a4.x; acc[3][1] += b4.w*a4.y; acc[3][2] += b4.w*a4.z; acc[3][3] += b4.w*a4.w;
        }
        if (m < 2) {
            float* dst = (m == 0) ? sQT : sKT;
            #pragma unroll
            for (int di = 0; di < 4; di++) {
                float4 o; o.x = acc[di][0]; o.y = acc[di][1]; o.z = acc[di][2]; o.w = acc[di][3];
                *reinterpret_cast<float4*>(dst + (d0+di)*VP + v0) = o;
            }
        } else {
            #pragma unroll
            for (int vi = 0; vi < 4; vi++) {
                if (v0 + vi < 25) {
                    #pragma unroll
                    for (int di = 0; di < 4; di++)
                        sVB[(v0+vi)*VB_S + d0 + di] = acc[di][vi];
                }
            }
        }
    } else {
        conv_tile(tid - 336, sFAT, convw, convb, sG);          // tiles 0..175
    }
    __syncthreads();

    // ---------------- S4: scores (196 thr) || conv tiles 176..335 ----------------
    if (tid < 196) {
        int h = tid / 49, rr = tid % 49;
        int wg = rr % 7, vqg = rr / 7;
        int w0 = wg * 4, vq0 = vqg * 4;
        const float* qb = sQT + h*16*VP;
        const float* kb = sKT + h*16*VP;
        float acc[4][4];
        #pragma unroll
        for (int i = 0; i < 4; i++)
            #pragma unroll
            for (int j = 0; j < 4; j++) acc[i][j] = 0.f;
        #pragma unroll 4
        for (int d = 0; d < 16; d++) {
            float4 a4 = *reinterpret_cast<const float4*>(qb + d*VP + vq0);
            float4 b4 = *reinterpret_cast<const float4*>(kb + d*VP + w0);
            acc[0][0] += b4.x*a4.x; acc[0][1] += b4.x*a4.y; acc[0][2] += b4.x*a4.z; acc[0][3] += b4.x*a4.w;
            acc[1][0] += b4.y*a4.x; acc[1][1] += b4.y*a4.y; acc[1][2] += b4.y*a4.z; acc[1][3] += b4.y*a4.w;
            acc[2][0] += b4.z*a4.x; acc[2][1] += b4.z*a4.y; acc[2][2] += b4.z*a4.z; acc[2][3] += b4.z*a4.w;
            acc[3][0] += b4.w*a4.x; acc[3][1] += b4.w*a4.y; acc[3][2] += b4.w*a4.z; acc[3][3] += b4.w*a4.w;
        }
        float* scb = sSC + h*700;
        #pragma unroll
        for (int wi = 0; wi < 4; wi++) {
            if (w0 + wi < 25) {
                float4 o; o.x = acc[wi][0]*0.25f; o.y = acc[wi][1]*0.25f;
                o.z = acc[wi][2]*0.25f; o.w = acc[wi][3]*0.25f;
                *reinterpret_cast<float4*>(scb + (w0+wi)*VP + vq0) = o;
            }
        }
    } else if (tid >= 352) {
        conv_tile(176 + (tid - 352), sFAT, convw, convb, sG);  // tiles 176..335
    }
    __syncthreads();

    // ---------------- S5: softmax over w (4 lanes per column, shfl) ----------------
    if (tid < 400) {
        int col = tid >> 2, sub = tid & 3;
        int h = col / 25, vq = col % 25;
        float* base = sSC + h*700 + vq;
        unsigned gm = 0xFu << ((tid & 31) & ~3);
        float mx = -1e30f;
        for (int w = sub; w < 25; w += 4) mx = fmaxf(mx, base[w*VP]);
        mx = fmaxf(mx, __shfl_xor_sync(gm, mx, 1));
        mx = fmaxf(mx, __shfl_xor_sync(gm, mx, 2));
        float s = 0.f;
        for (int w = sub; w < 25; w += 4) s += __expf(base[w*VP] - mx);
        s += __shfl_xor_sync(gm, s, 1);
        s += __shfl_xor_sync(gm, s, 2);
        float inv = 1.f / s;
        for (int w = sub; w < 25; w += 4) base[w*VP] = __expf(base[w*VP] - mx) * inv;
    }
    __syncthreads();

    // ---------------- S6: xoT[e][v] = sum_w attn[h][w][v] * vB[w][e] ----------
    if (tid < 112) {
        int vg = tid % 7, eg = tid / 7;
        int v0 = vg * 4, e0 = eg * 4;
        int h = eg >> 2;
        const float* scb = sSC + h*700;
        float acc[4][4];
        #pragma unroll
        for (int i = 0; i < 4; i++)
            #pragma unroll
            for (int j = 0; j < 4; j++) acc[i][j] = 0.f;
        #pragma unroll 5
        for (int w = 0; w < 25; w++) {
            float4 a4 = *reinterpret_cast<const float4*>(sVB + w*VB_S + e0);
            float4 b4 = *reinterpret_cast<const float4*>(scb + w*VP + v0);
            acc[0][0] += a4.x*b4.x; acc[0][1] += a4.x*b4.y; acc[0][2] += a4.x*b4.z; acc[0][3] += a4.x*b4.w;
            acc[1][0] += a4.y*b4.x; acc[1][1] += a4.y*b4.y; acc[1][2] += a4.y*b4.z; acc[1][3] += a4.y*b4.w;
            acc[2][0] += a4.z*b4.x; acc[2][1] += a4.z*b4.y; acc[2][2] += a4.z*b4.z; acc[2][3] += a4.z*b4.w;
            acc[3][0] += a4.w*b4.x; acc[3][1] += a4.w*b4.y; acc[3][2] += a4.w*b4.z; acc[3][3] += a4.w*b4.w;
        }
        #pragma unroll
        for (int ei = 0; ei < 4; ei++) {
            float4 o; o.x = acc[ei][0]; o.y = acc[ei][1]; o.z = acc[ei][2]; o.w = acc[ei][3];
            *reinterpret_cast<float4*>(sXOT + (e0+ei)*VP + v0) = o;
        }
    }
    __syncthreads();

    // ---------------- S7: fused merge (single 4x4 accumulator) ---------------
    // out = relu(bn2( 0.5*(g x A) + 0.5*gate*res + 0.5*gate*(xo @ fc_w) ))
    if (tid < 112) {
        int vg = tid % 7, cg = tid / 7;
        int v0 = vg * 4, c0 = cg * 4;
        float gs = 0.5f * sGate[0];
        float acc[4][4];                     // [wi][coi]
        #pragma unroll
        for (int i = 0; i < 4; i++)
            #pragma unroll
            for (int j = 0; j < 4; j++) acc[i][j] = 0.f;
        // g x A
        #pragma unroll 5
        for (int kv = 0; kv < 75; kv++) {
            float4 a4 = *reinterpret_cast<const float4*>(sA + kv*VP + v0);
            float4 b4 = *reinterpret_cast<const float4*>(sG + kv*64 + c0);
            acc[0][0] += a4.x*b4.x; acc[0][1] += a4.x*b4.y; acc[0][2] += a4.x*b4.z; acc[0][3] += a4.x*b4.w;
            acc[1][0] += a4.y*b4.x; acc[1][1] += a4.y*b4.y; acc[1][2] += a4.y*b4.z; acc[1][3] += a4.y*b4.w;
            acc[2][0] += a4.z*b4.x; acc[2][1] += a4.z*b4.y; acc[2][2] += a4.z*b4.z; acc[2][3] += a4.z*b4.w;
            acc[3][0] += a4.w*b4.x; acc[3][1] += a4.w*b4.y; acc[3][2] += a4.w*b4.z; acc[3][3] += a4.w*b4.w;
        }
        // scale by 0.5 and add gated residual
        #pragma unroll
        for (int wi = 0; wi < 4; wi++)
            #pragma unroll
            for (int ci = 0; ci < 4; ci++)
                acc[wi][ci] = 0.5f*acc[wi][ci] + gs * sFAT[(c0+ci)*VP + v0 + wi];
        // gs * (xo @ fc_w)
        #pragma unroll 4
        for (int e = 0; e < 64; e++) {
            float4 a4 = *reinterpret_cast<const float4*>(sXOT + e*VP + v0);
            a4.x *= gs; a4.y *= gs; a4.z *= gs; a4.w *= gs;
            float4 b4 = *reinterpret_cast<const float4*>(fcw + e*64 + c0);
            acc[0][0] += a4.x*b4.x; acc[0][1] += a4.x*b4.y; acc[0][2] += a4.x*b4.z; acc[0][3] += a4.x*b4.w;
            acc[1][0] += a4.y*b4.x; acc[1][1] += a4.y*b4.y; acc[1][2] += a4.y*b4.z; acc[1][3] += a4.y*b4.w;
            acc[2][0] += a4.z*b4.x; acc[2][1] += a4.z*b4.y; acc[2][2] += a4.z*b4.z; acc[2][3] += a4.z*b4.w;
            acc[3][0] += a4.w*b4.x; acc[3][1] += a4.w*b4.y; acc[3][2] += a4.w*b4.z; acc[3][3] += a4.w*b4.w;
        }
        // bn2 + relu + store
        #pragma unroll
        for (int coi = 0; coi < 4; coi++) {
            int co = c0 + coi;
            float s2 = sB2S[co], b2 = sB2B[co];
            float* ob = out + ((size_t)(n*64 + co))*7500 + t*25;
            #pragma unroll
            for (int wi = 0; wi < 4; wi++) {
                int w = v0 + wi;
                if (w < 25)
                    ob[w] = fmaxf(acc[wi][coi] * s2 + b2, 0.f);
            }
        }
    }
}

extern "C" void kernel_launch(void* const* d_in, const int* in_sizes, int n_in,
                              void* d_out, int out_size) {
    const float* x     = (const float*)d_in[0];
    const float* Ag    = (const float*)d_in[1];
    const float* bn1g  = (const float*)d_in[2];
    const float* bn1b  = (const float*)d_in[3];
    const float* bn1m  = (const float*)d_in[4];
    const float* bn1v  = (const float*)d_in[5];
    const float* convw = (const float*)d_in[6];
    const float* convb = (const float*)d_in[7];
    const float* lng   = (const float*)d_in[8];
    const float* lnb   = (const float*)d_in[9];
    const float* wq    = (const float*)d_in[10];
    const float* wk    = (const float*)d_in[11];
    const float* wv    = (const float*)d_in[12];
    const float* fcw   = (const float*)d_in[13];
    const float* gatep = (const float*)d_in[14];
    const float* bn2g  = (const float*)d_in[15];
    const float* bn2b  = (const float*)d_in[16];
    const float* bn2m  = (const float*)d_in[17];
    const float* bn2v  = (const float*)d_in[18];
    float* outp = (float*)d_out;

    (void)cudaFuncSetAttribute(intentgcn_kernel,
                               cudaFuncAttributeMaxDynamicSharedMemorySize, SMEM_BYTES);
    dim3 grid(300, 32);
    intentgcn_kernel<<<grid, 512, SMEM_BYTES>>>(
        x, Ag, bn1g, bn1b, bn1m, bn1v, convw, convb, lng, lnb,
        wq, wk, wv, fcw, gatep, bn2g, bn2b, bn2m, bn2v, outp);
}

// round 8
// speedup vs baseline: 1.2241x; 1.2241x over previous
#include <cuda_runtime.h>

// IntentGCN fused kernel v5: v2 base (64 regs, 2x512 blocks/SM, float4 tiles,
// weights via LDG) + widened narrow phases (LN/softmax/P4/P5+P7) for latency hiding.
// N=32, C_IN=C_OUT=64, K=3, T=300, V=25, H=4, DK=DV=16.

#define VP 28    // padded v (stride for [*][v] arrays)
#define VB_S 68  // stride for [v][64] arrays

// shared memory float offsets (v2 map; OF_FA2 region now unused)
#define OF_FAT  0        // faT[64][28]
#define OF_QNT  1792     // qnT[64][28]
#define OF_QT   3584     // qT[64][28]
#define OF_KT   5376     // kT[64][28]
#define OF_VB   7168     // vB[25][68]
#define OF_SC   8868     // scT[4][28][28]
#define OF_XOT  12004    // xoT[64][28]
#define OF_G    15496    // g[75][64]
#define OF_A    20296    // A[75][28]
#define OF_MISC 22396
#define SMEM_FLOATS 22852
#define SMEM_BYTES (SMEM_FLOATS * 4)

// One conv-branch output tile (request-lean float4-weight form).
// g[k][v0..v0+3][co0..co0+3] = fa @ conv_w[k]^T + bias
__device__ __forceinline__ void conv_tile(int tt, const float* __restrict__ sFAT,
                                          const float* __restrict__ convw,
                                          const float* __restrict__ convb,
                                          float* __restrict__ sG)
{
    int k = tt / 112, r = tt % 112;
    int vg = r % 7, cog = r / 7;
    int v0 = vg * 4, co0 = cog * 4;
    const float* wb = convw + (k*64 + co0) * 64;
    float acc[4][4];
    #pragma unroll
    for (int coi = 0; coi < 4; coi++) {
        float bv = convb[k*64 + co0 + coi];
        #pragma unroll
        for (int vi = 0; vi < 4; vi++) acc[vi][coi] = bv;
    }
    #pragma unroll 2
    for (int ci0 = 0; ci0 < 64; ci0 += 4) {
        float4 rb0 = *reinterpret_cast<const float4*>(wb + 0*64 + ci0);
        float4 rb1 = *reinterpret_cast<const float4*>(wb + 1*64 + ci0);
        float4 rb2 = *reinterpret_cast<const float4*>(wb + 2*64 + ci0);
        float4 rb3 = *reinterpret_cast<const float4*>(wb + 3*64 + ci0);
        #pragma unroll
        for (int j = 0; j < 4; j++) {
            float4 la = *reinterpret_cast<const float4*>(sFAT + (ci0+j)*VP + v0);
            float w0v = (j==0)?rb0.x:((j==1)?rb0.y:((j==2)?rb0.z:rb0.w));
            float w1v = (j==0)?rb1.x:((j==1)?rb1.y:((j==2)?rb1.z:rb1.w));
            float w2v = (j==0)?rb2.x:((j==1)?rb2.y:((j==2)?rb2.z:rb2.w));
            float w3v = (j==0)?rb3.x:((j==1)?rb3.y:((j==2)?rb3.z:rb3.w));
            acc[0][0] += la.x*w0v; acc[0][1] += la.x*w1v; acc[0][2] += la.x*w2v; acc[0][3] += la.x*w3v;
            acc[1][0] += la.y*w0v; acc[1][1] += la.y*w1v; acc[1][2] += la.y*w2v; acc[1][3] += la.y*w3v;
            acc[2][0] += la.z*w0v; acc[2][1] += la.z*w1v; acc[2][2] += la.z*w2v; acc[2][3] += la.z*w3v;
            acc[3][0] += la.w*w0v; acc[3][1] += la.w*w1v; acc[3][2] += la.w*w2v; acc[3][3] += la.w*w3v;
        }
    }
    #pragma unroll
    for (int vi = 0; vi < 4; vi++) {
        if (v0 + vi < 25) {
            float4 o; o.x = acc[vi][0]; o.y = acc[vi][1]; o.z = acc[vi][2]; o.w = acc[vi][3];
            *reinterpret_cast<float4*>(sG + (k*25 + v0 + vi)*64 + co0) = o;
        }
    }
}

__global__ __launch_bounds__(512, 2)
void intentgcn_kernel(
    const float* __restrict__ x,    const float* __restrict__ Ag,
    const float* __restrict__ bn1g, const float* __restrict__ bn1b,
    const float* __restrict__ bn1m, const float* __restrict__ bn1v,
    const float* __restrict__ convw, const float* __restrict__ convb,
    const float* __restrict__ lng,  const float* __restrict__ lnb,
    const float* __restrict__ wq,   const float* __restrict__ wk,
    const float* __restrict__ wv,   const float* __restrict__ fcw,
    const float* __restrict__ gatep,
    const float* __restrict__ bn2g, const float* __restrict__ bn2b,
    const float* __restrict__ bn2m, const float* __restrict__ bn2v,
    float* __restrict__ out)
{
    extern __shared__ float sm[];
    float* sFAT = sm + OF_FAT;
    float* sQNT = sm + OF_QNT;
    float* sQT  = sm + OF_QT;
    float* sKT  = sm + OF_KT;
    float* sVB  = sm + OF_VB;
    float* sSC  = sm + OF_SC;
    float* sXOT = sm + OF_XOT;
    float* sG   = sm + OF_G;
    float* sA   = sm + OF_A;
    float* sB1S = sm + OF_MISC;
    float* sB1B = sB1S + 64;
    float* sB2S = sB1B + 64;
    float* sB2B = sB2S + 64;
    float* sLNg = sB2B + 64;
    float* sLNb = sLNg + 64;
    float* sMU  = sLNb + 64;   // 32
    float* sRS  = sMU + 32;    // 32
    float* sGate = sRS + 32;

    const int tid = threadIdx.x;
    const int t = blockIdx.x;
    const int n = blockIdx.y;

    // ---------------- S0: params, A, pad-zeroing, bn1 ----------------
    if (tid < 64) {
        float s1 = bn1g[tid] * rsqrtf(bn1v[tid] + 1e-5f);
        sB1S[tid] = s1;
        sB1B[tid] = bn1b[tid] - bn1m[tid] * s1;
        float s2 = bn2g[tid] * rsqrtf(bn2v[tid] + 1e-5f);
        sB2S[tid] = s2;
        sB2B[tid] = bn2b[tid] - bn2m[tid] * s2;
        sLNg[tid] = lng[tid];
        sLNb[tid] = lnb[tid];
    }
    if (tid == 0) sGate[0] = gatep[0];
    for (int i = tid; i < 192; i += 512) {           // zero padded v-cols
        int c = i / 3, vp = 25 + i % 3;
        sFAT[c*VP + vp] = 0.f;
        sQNT[c*VP + vp] = 0.f;
    }
    for (int i = tid; i < 225; i += 512)             // zero padded A w-cols
        sA[(i/3)*VP + 25 + i % 3] = 0.f;
    for (int i = tid; i < 1875; i += 512) {          // A[75][25] -> stride 28
        int kv = i / 25, w = i - kv*25;
        sA[kv*VP + w] = Ag[i];
    }
    __syncthreads();

    const float* xb = x + (size_t)(n*64*300 + t) * 25;
    for (int i = tid; i < 1600; i += 512) {
        int c = i / 25, v = i - c*25;
        sFAT[c*VP + v] = xb[c*7500 + v] * sB1S[c] + sB1B[c];
    }
    __syncthreads();

    // ---------------- S1: per-token LayerNorm stats (parallel shfl tree) -----
    if (tid < 256) {
        int v = tid >> 3;
        int j = tid & 7;
        int vv = (v < 25) ? v : 24;
        float s = 0.f, s2 = 0.f;
        #pragma unroll
        for (int cc = 0; cc < 8; cc++) {
            float xv = sFAT[(j*8 + cc)*VP + vv];
            s += xv; s2 += xv*xv;
        }
        s  += __shfl_down_sync(0xFFFFFFFFu, s, 4);
        s2 += __shfl_down_sync(0xFFFFFFFFu, s2, 4);
        s  += __shfl_down_sync(0xFFFFFFFFu, s, 2);
        s2 += __shfl_down_sync(0xFFFFFFFFu, s2, 2);
        s  += __shfl_down_sync(0xFFFFFFFFu, s, 1);
        s2 += __shfl_down_sync(0xFFFFFFFFu, s2, 1);
        if (j == 0 && v < 25) {
            float mu = s * (1.f/64.f);
            float var = s2 * (1.f/64.f) - mu*mu;
            sMU[v] = mu;
            sRS[v] = rsqrtf(var + 1e-6f);
        }
    }
    __syncthreads();

    // ---------------- S2: qn (transposed) ----------------
    for (int i = tid; i < 1600; i += 512) {
        int c = i / 25, v = i - c*25;
        sQNT[c*VP + v] = (sFAT[c*VP + v] - sMU[v]) * sRS[v] * sLNg[c] + sLNb[c];
    }
    __syncthreads();

    // ---------------- S3: q/k/v projections (336 thr, 4x4 tiles) -------------
    if (tid < 336) {
        int m = tid / 112, r = tid % 112;
        int vg = r % 7, dg = r / 7;
        int v0 = vg * 4, d0 = dg * 4;
        const float* src = (m == 0) ? sQNT : sFAT;
        const float* wsel = (m == 0) ? wq : ((m == 1) ? wk : wv);
        float acc[4][4];
        #pragma unroll
        for (int i = 0; i < 4; i++)
            #pragma unroll
            for (int j = 0; j < 4; j++) acc[i][j] = 0.f;
        #pragma unroll 4
        for (int c = 0; c < 64; c++) {
            float4 a4 = *reinterpret_cast<const float4*>(src + c*VP + v0);
            float4 b4 = *reinterpret_cast<const float4*>(wsel + c*64 + d0);
            acc[0][0] += b4.x*a4.x; acc[0][1] += b4.x*a4.y; acc[0][2] += b4.x*a4.z; acc[0][3] += b4.x*a4.w;
            acc[1][0] += b4.y*a4.x; acc[1][1] += b4.y*a4.y; acc[1][2] += b4.y*a4.z; acc[1][3] += b4.y*a4.w;
            acc[2][0] += b4.z*a4.x; acc[2][1] += b4.z*a4.y; acc[2][2] += b4.z*a4.z; acc[2][3] += b4.z*a4.w;
            acc[3][0] += b4.w*a4.x; acc[3][1] += b4.w*a4.y; acc[3][2] += b4.w*a4.z; acc[3][3] += b4.w*a4.w;
        }
        if (m < 2) {
            float* dst = (m == 0) ? sQT : sKT;
            #pragma unroll
            for (int di = 0; di < 4; di++) {
                float4 o; o.x = acc[di][0]; o.y = acc[di][1]; o.z = acc[di][2]; o.w = acc[di][3];
                *reinterpret_cast<float4*>(dst + (d0+di)*VP + v0) = o;
            }
        } else {
            #pragma unroll
            for (int vi = 0; vi < 4; vi++) {
                if (v0 + vi < 25) {
                    #pragma unroll
                    for (int di = 0; di < 4; di++)
                        sVB[(v0+vi)*VB_S + d0 + di] = acc[di][vi];
                }
            }
        }
    }
    __syncthreads();

    // ---------------- S4: scores scT[h][w][vq] = (q.k)/4 (196 thr) -----------
    if (tid < 196) {
        int h = tid / 49, rr = tid % 49;
        int wg = rr % 7, vqg = rr / 7;
        int w0 = wg * 4, vq0 = vqg * 4;
        const float* qb = sQT + h*16*VP;
        const float* kb = sKT + h*16*VP;
        float acc[4][4];
        #pragma unroll
        for (int i = 0; i < 4; i++)
            #pragma unroll
            for (int j = 0; j < 4; j++) acc[i][j] = 0.f;
        #pragma unroll 4
        for (int d = 0; d < 16; d++) {
            float4 a4 = *reinterpret_cast<const float4*>(qb + d*VP + vq0);
            float4 b4 = *reinterpret_cast<const float4*>(kb + d*VP + w0);
            acc[0][0] += b4.x*a4.x; acc[0][1] += b4.x*a4.y; acc[0][2] += b4.x*a4.z; acc[0][3] += b4.x*a4.w;
            acc[1][0] += b4.y*a4.x; acc[1][1] += b4.y*a4.y; acc[1][2] += b4.y*a4.z; acc[1][3] += b4.y*a4.w;
            acc[2][0] += b4.z*a4.x; acc[2][1] += b4.z*a4.y; acc[2][2] += b4.z*a4.z; acc[2][3] += b4.z*a4.w;
            acc[3][0] += b4.w*a4.x; acc[3][1] += b4.w*a4.y; acc[3][2] += b4.w*a4.z; acc[3][3] += b4.w*a4.w;
        }
        float* scb = sSC + h*784;
        #pragma unroll
        for (int wi = 0; wi < 4; wi++) {
            float4 o; o.x = acc[wi][0]*0.25f; o.y = acc[wi][1]*0.25f;
            o.z = acc[wi][2]*0.25f; o.w = acc[wi][3]*0.25f;
            *reinterpret_cast<float4*>(scb + (w0+wi)*VP + vq0) = o;
        }
    }
    __syncthreads();

    // ---------------- S5: softmax over w (parallel, 4 lanes per column) ------
    if (tid < 400) {
        int col = tid >> 2, sub = tid & 3;
        int h = col / 25, vq = col % 25;
        float* base = sSC + h*784 + vq;
        unsigned gm = 0xFu << ((tid & 31) & ~3);
        float mx = -1e30f;
        for (int w = sub; w < 25; w += 4) mx = fmaxf(mx, base[w*VP]);
        mx = fmaxf(mx, __shfl_xor_sync(gm, mx, 1));
        mx = fmaxf(mx, __shfl_xor_sync(gm, mx, 2));
        float s = 0.f;
        for (int w = sub; w < 25; w += 4) s += __expf(base[w*VP] - mx);
        s += __shfl_xor_sync(gm, s, 1);
        s += __shfl_xor_sync(gm, s, 2);
        float inv = 1.f / s;
        for (int w = sub; w < 25; w += 4) base[w*VP] = __expf(base[w*VP] - mx) * inv;
    }
    __syncthreads();

    // ---------------- S6: xoT (224 thr, 2x4 tiles) || conv (288 thr) ---------
    if (tid < 224) {
        int vg = tid % 7, eh = tid / 7;      // eh 0..31
        int v0 = vg * 4, e0 = eh * 2;
        int h = e0 >> 4;
        const float* scb = sSC + h*784;
        float a00=0.f,a01=0.f,a02=0.f,a03=0.f;
        float a10=0.f,a11=0.f,a12=0.f,a13=0.f;
        #pragma unroll 5
        for (int w = 0; w < 25; w++) {
            float2 vv = *reinterpret_cast<const float2*>(sVB + w*VB_S + e0);
            float4 b4 = *reinterpret_cast<const float4*>(scb + w*VP + v0);
            a00 += vv.x*b4.x; a01 += vv.x*b4.y; a02 += vv.x*b4.z; a03 += vv.x*b4.w;
            a10 += vv.y*b4.x; a11 += vv.y*b4.y; a12 += vv.y*b4.z; a13 += vv.y*b4.w;
        }
        float4 o0; o0.x=a00; o0.y=a01; o0.z=a02; o0.w=a03;
        float4 o1; o1.x=a10; o1.y=a11; o1.z=a12; o1.w=a13;
        *reinterpret_cast<float4*>(sXOT + (e0+0)*VP + v0) = o0;
        *reinterpret_cast<float4*>(sXOT + (e0+1)*VP + v0) = o1;
    } else {
        int ci = tid - 224;                  // 0..287
        conv_tile(ci, sFAT, convw, convb, sG);
        if (ci < 48)
            conv_tile(288 + ci, sFAT, convw, convb, sG);
    }
    __syncthreads();

    // ---------------- S7: fused merge, 224 thr, 4x2 tiles --------------------
    // out = relu(bn2( 0.5*(g x A) + 0.5*gate*res + 0.5*gate*(xo @ fc_w) ))
    if (tid < 224) {
        int vg = tid % 7, cg = tid / 7;      // cg 0..31
        int v0 = vg * 4, c0 = cg * 2;
        float gs = 0.5f * sGate[0];
        float acc[4][2];                     // [wi][coi]
        #pragma unroll
        for (int i = 0; i < 4; i++) { acc[i][0] = 0.f; acc[i][1] = 0.f; }
        // g x A
        #pragma unroll 5
        for (int kv = 0; kv < 75; kv++) {
            float4 a4 = *reinterpret_cast<const float4*>(sA + kv*VP + v0);
            float2 g2 = *reinterpret_cast<const float2*>(sG + kv*64 + c0);
            acc[0][0] += a4.x*g2.x; acc[0][1] += a4.x*g2.y;
            acc[1][0] += a4.y*g2.x; acc[1][1] += a4.y*g2.y;
            acc[2][0] += a4.z*g2.x; acc[2][1] += a4.z*g2.y;
            acc[3][0] += a4.w*g2.x; acc[3][1] += a4.w*g2.y;
        }
        // halve + gated residual
        #pragma unroll
        for (int wi = 0; wi < 4; wi++)
            #pragma unroll
            for (int ci = 0; ci < 2; ci++)
                acc[wi][ci] = 0.5f*acc[wi][ci] + gs * sFAT[(c0+ci)*VP + v0 + wi];
        // gs * (xo @ fc_w)
        #pragma unroll 4
        for (int e = 0; e < 64; e++) {
            float4 x4 = *reinterpret_cast<const float4*>(sXOT + e*VP + v0);
            x4.x *= gs; x4.y *= gs; x4.z *= gs; x4.w *= gs;
            float2 w2 = *reinterpret_cast<const float2*>(fcw + e*64 + c0);
            acc[0][0] += x4.x*w2.x; acc[0][1] += x4.x*w2.y;
            acc[1][0] += x4.y*w2.x; acc[1][1] += x4.y*w2.y;
            acc[2][0] += x4.z*w2.x; acc[2][1] += x4.z*w2.y;
            acc[3][0] += x4.w*w2.x; acc[3][1] += x4.w*w2.y;
        }
        // bn2 + relu + store
        #pragma unroll
        for (int ci = 0; ci < 2; ci++) {
            int co = c0 + ci;
            float s2 = sB2S[co], b2 = sB2B[co];
            float* ob = out + ((size_t)(n*64 + co))*7500 + t*25;
            #pragma unroll
            for (int wi = 0; wi < 4; wi++) {
                int w = v0 + wi;
                if (w < 25)
                    ob[w] = fmaxf(acc[wi][ci] * s2 + b2, 0.f);
            }
        }
    }
}

extern "C" void kernel_launch(void* const* d_in, const int* in_sizes, int n_in,
                              void* d_out, int out_size) {
    const float* x     = (const float*)d_in[0];
    const float* Ag    = (const float*)d_in[1];
    const float* bn1g  = (const float*)d_in[2];
    const float* bn1b  = (const float*)d_in[3];
    const float* bn1m  = (const float*)d_in[4];
    const float* bn1v  = (const float*)d_in[5];
    const float* convw = (const float*)d_in[6];
    const float* convb = (const float*)d_in[7];
    const float* lng   = (const float*)d_in[8];
    const float* lnb   = (const float*)d_in[9];
    const float* wq    = (const float*)d_in[10];
    const float* wk    = (const float*)d_in[11];
    const float* wv    = (const float*)d_in[12];
    const float* fcw   = (const float*)d_in[13];
    const float* gatep = (const float*)d_in[14];
    const float* bn2g  = (const float*)d_in[15];
    const float* bn2b  = (const float*)d_in[16];
    const float* bn2m  = (const float*)d_in[17];
    const float* bn2v  = (const float*)d_in[18];
    float* outp = (float*)d_out;

    (void)cudaFuncSetAttribute(intentgcn_kernel,
                               cudaFuncAttributeMaxDynamicSharedMemorySize, SMEM_BYTES);
    dim3 grid(300, 32);
    intentgcn_kernel<<<grid, 512, SMEM_BYTES>>>(
        x, Ag, bn1g, bn1b, bn1m, bn1v, convw, convb, lng, lnb,
        wq, wk, wv, fcw, gatep, bn2g, bn2b, bn2m, bn2v, outp);
}

// round 10
// speedup vs baseline: 1.3534x; 1.1056x over previous
#include <cuda_runtime.h>

// IntentGCN fused kernel v6: v2 base + 8-wide-v register tiles in S3/conv
// (halves weight-LDG per FMA), float4 qn, parallel LN/softmax.
// N=32, C_IN=C_OUT=64, K=3, T=300, V=25, H=4, DK=DV=16.

#define VP 28    // padded v (stride for [*][v] arrays)
#define VB_S 68  // stride for [v][64] and fa2 arrays

// shared memory float offsets (v2 map)
#define OF_FAT  0        // faT[64][28]
#define OF_QNT  1792     // qnT[64][28]
#define OF_QT   3584     // qT[64][28]
#define OF_KT   5376     // kT[64][28]
#define OF_VB   7168     // vB[25][68]
#define OF_SC   8868     // scT[4][28][28]
#define OF_XOT  12004    // xoT[64][28]
#define OF_FA2  13796    // fa2[25][68]
#define OF_G    15496    // g[75][64]
#define OF_A    20296    // A[75][28]
#define OF_MISC 22396
#define SMEM_FLOATS 22852
#define SMEM_BYTES (SMEM_FLOATS * 4)

// Conv tile, 4co x 8v: g[k][v0..v0+7][co0..co0+3] = fa @ conv_w[k]^T + bias
// ct in 0..191
__device__ __forceinline__ void conv_tile8(int ct, const float* __restrict__ sFAT,
                                           const float* __restrict__ convw,
                                           const float* __restrict__ convb,
                                           float* __restrict__ sG)
{
    int k = ct / 64, rr = ct % 64;
    int cog = rr >> 2, vg8 = rr & 3;
    int co0 = cog * 4, v0 = vg8 * 8;
    const float* wb = convw + (k*64 + co0) * 64;
    float acc[8][4];                     // [vi][coi]
    #pragma unroll
    for (int coi = 0; coi < 4; coi++) {
        float bv = convb[k*64 + co0 + coi];
        #pragma unroll
        for (int vi = 0; vi < 8; vi++) acc[vi][coi] = bv;
    }
    #pragma unroll 2
    for (int ci0 = 0; ci0 < 64; ci0 += 4) {
        float4 rb0 = *reinterpret_cast<const float4*>(wb + 0*64 + ci0);
        float4 rb1 = *reinterpret_cast<const float4*>(wb + 1*64 + ci0);
        float4 rb2 = *reinterpret_cast<const float4*>(wb + 2*64 + ci0);
        float4 rb3 = *reinterpret_cast<const float4*>(wb + 3*64 + ci0);
        #pragma unroll
        for (int j = 0; j < 4; j++) {
            float4 la = *reinterpret_cast<const float4*>(sFAT + (ci0+j)*VP + v0);
            float4 lb = *reinterpret_cast<const float4*>(sFAT + (ci0+j)*VP + v0 + 4);
            float w0v = (j==0)?rb0.x:((j==1)?rb0.y:((j==2)?rb0.z:rb0.w));
            float w1v = (j==0)?rb1.x:((j==1)?rb1.y:((j==2)?rb1.z:rb1.w));
            float w2v = (j==0)?rb2.x:((j==1)?rb2.y:((j==2)?rb2.z:rb2.w));
            float w3v = (j==0)?rb3.x:((j==1)?rb3.y:((j==2)?rb3.z:rb3.w));
            acc[0][0] += la.x*w0v; acc[0][1] += la.x*w1v; acc[0][2] += la.x*w2v; acc[0][3] += la.x*w3v;
            acc[1][0] += la.y*w0v; acc[1][1] += la.y*w1v; acc[1][2] += la.y*w2v; acc[1][3] += la.y*w3v;
            acc[2][0] += la.z*w0v; acc[2][1] += la.z*w1v; acc[2][2] += la.z*w2v; acc[2][3] += la.z*w3v;
            acc[3][0] += la.w*w0v; acc[3][1] += la.w*w1v; acc[3][2] += la.w*w2v; acc[3][3] += la.w*w3v;
            acc[4][0] += lb.x*w0v; acc[4][1] += lb.x*w1v; acc[4][2] += lb.x*w2v; acc[4][3] += lb.x*w3v;
            acc[5][0] += lb.y*w0v; acc[5][1] += lb.y*w1v; acc[5][2] += lb.y*w2v; acc[5][3] += lb.y*w3v;
            acc[6][0] += lb.z*w0v; acc[6][1] += lb.z*w1v; acc[6][2] += lb.z*w2v; acc[6][3] += lb.z*w3v;
            acc[7][0] += lb.w*w0v; acc[7][1] += lb.w*w1v; acc[7][2] += lb.w*w2v; acc[7][3] += lb.w*w3v;
        }
    }
    #pragma unroll
    for (int vi = 0; vi < 8; vi++) {
        if (v0 + vi < 25) {
            float4 o; o.x = acc[vi][0]; o.y = acc[vi][1]; o.z = acc[vi][2]; o.w = acc[vi][3];
            *reinterpret_cast<float4*>(sG + (k*25 + v0 + vi)*64 + co0) = o;
        }
    }
}

__global__ __launch_bounds__(512, 2)
void intentgcn_kernel(
    const float* __restrict__ x,    const float* __restrict__ Ag,
    const float* __restrict__ bn1g, const float* __restrict__ bn1b,
    const float* __restrict__ bn1m, const float* __restrict__ bn1v,
    const float* __restrict__ convw, const float* __restrict__ convb,
    const float* __restrict__ lng,  const float* __restrict__ lnb,
    const float* __restrict__ wq,   const float* __restrict__ wk,
    const float* __restrict__ wv,   const float* __restrict__ fcw,
    const float* __restrict__ gatep,
    const float* __restrict__ bn2g, const float* __restrict__ bn2b,
    const float* __restrict__ bn2m, const float* __restrict__ bn2v,
    float* __restrict__ out)
{
    extern __shared__ float sm[];
    float* sFAT = sm + OF_FAT;
    float* sQNT = sm + OF_QNT;
    float* sQT  = sm + OF_QT;
    float* sKT  = sm + OF_KT;
    float* sVB  = sm + OF_VB;
    float* sSC  = sm + OF_SC;
    float* sXOT = sm + OF_XOT;
    float* sFA2 = sm + OF_FA2;
    float* sG   = sm + OF_G;
    float* sA   = sm + OF_A;
    float* sB1S = sm + OF_MISC;
    float* sB1B = sB1S + 64;
    float* sB2S = sB1B + 64;
    float* sB2B = sB2S + 64;
    float* sLNg = sB2B + 64;
    float* sLNb = sLNg + 64;
    float* sMU  = sLNb + 64;   // 32
    float* sRS  = sMU + 32;    // 32
    float* sGate = sRS + 32;

    const int tid = threadIdx.x;
    const int t = blockIdx.x;
    const int n = blockIdx.y;

    // ---------------- S0: params, A, pad-zeroing, bn1 ----------------
    if (tid < 64) {
        float s1 = bn1g[tid] * rsqrtf(bn1v[tid] + 1e-5f);
        sB1S[tid] = s1;
        sB1B[tid] = bn1b[tid] - bn1m[tid] * s1;
        float s2 = bn2g[tid] * rsqrtf(bn2v[tid] + 1e-5f);
        sB2S[tid] = s2;
        sB2B[tid] = bn2b[tid] - bn2m[tid] * s2;
        sLNg[tid] = lng[tid];
        sLNb[tid] = lnb[tid];
    }
    if (tid == 0) sGate[0] = gatep[0];
    for (int i = tid; i < 192; i += 512) {           // zero padded v-cols
        int c = i / 3, vp = 25 + i % 3;
        sFAT[c*VP + vp] = 0.f;
        sQNT[c*VP + vp] = 0.f;
    }
    for (int i = tid; i < 225; i += 512)             // zero padded A w-cols
        sA[(i/3)*VP + 25 + i % 3] = 0.f;
    for (int i = tid; i < 1875; i += 512) {          // A[75][25] -> stride 28
        int kv = i / 25, w = i - kv*25;
        sA[kv*VP + w] = Ag[i];
    }
    __syncthreads();

    const float* xb = x + (size_t)(n*64*300 + t) * 25;
    for (int i = tid; i < 1600; i += 512) {
        int c = i / 25, v = i - c*25;
        sFAT[c*VP + v] = xb[c*7500 + v] * sB1S[c] + sB1B[c];
    }
    __syncthreads();

    // ---------------- S1: per-token LayerNorm stats (parallel shfl tree) -----
    if (tid < 256) {
        int v = tid >> 3;
        int j = tid & 7;
        int vv = (v < 25) ? v : 24;
        float s = 0.f, s2 = 0.f;
        #pragma unroll
        for (int cc = 0; cc < 8; cc++) {
            float xv = sFAT[(j*8 + cc)*VP + vv];
            s += xv; s2 += xv*xv;
        }
        s  += __shfl_down_sync(0xFFFFFFFFu, s, 4);
        s2 += __shfl_down_sync(0xFFFFFFFFu, s2, 4);
        s  += __shfl_down_sync(0xFFFFFFFFu, s, 2);
        s2 += __shfl_down_sync(0xFFFFFFFFu, s2, 2);
        s  += __shfl_down_sync(0xFFFFFFFFu, s, 1);
        s2 += __shfl_down_sync(0xFFFFFFFFu, s2, 1);
        if (j == 0 && v < 25) {
            float mu = s * (1.f/64.f);
            float var = s2 * (1.f/64.f) - mu*mu;
            sMU[v] = mu;
            sRS[v] = rsqrtf(var + 1e-6f);
        }
    }
    __syncthreads();

    // ---------------- S2: qn (float4) ----------------
    if (tid < 448) {
        int c = tid / 7, j = tid % 7;
        float lg = sLNg[c], lb = sLNb[c];
        if (j < 6) {
            int v0 = j * 4;
            float4 f4 = *reinterpret_cast<const float4*>(sFAT + c*VP + v0);
            float4 m4 = *reinterpret_cast<const float4*>(sMU + v0);
            float4 r4 = *reinterpret_cast<const float4*>(sRS + v0);
            float4 o;
            o.x = (f4.x - m4.x) * r4.x * lg + lb;
            o.y = (f4.y - m4.y) * r4.y * lg + lb;
            o.z = (f4.z - m4.z) * r4.z * lg + lb;
            o.w = (f4.w - m4.w) * r4.w * lg + lb;
            *reinterpret_cast<float4*>(sQNT + c*VP + v0) = o;
        } else {
            sQNT[c*VP + 24] = (sFAT[c*VP + 24] - sMU[24]) * sRS[24] * lg + lb;
        }
    }
    __syncthreads();

    // ---------------- S3: q/k/v projections (192 thr, 4d x 8v tiles) ---------
    if (tid < 192) {
        int m = tid >> 6, r = tid & 63;
        int vg8 = r & 3, dg = r >> 2;
        int v0 = vg8 * 8, d0 = dg * 4;
        const float* src = (m == 0) ? sQNT : sFAT;
        const float* wsel = (m == 0) ? wq : ((m == 1) ? wk : wv);
        float acc[4][8];                 // [di][vi]
        #pragma unroll
        for (int i = 0; i < 4; i++)
            #pragma unroll
            for (int j = 0; j < 8; j++) acc[i][j] = 0.f;
        #pragma unroll 4
        for (int c = 0; c < 64; c++) {
            float4 a4 = *reinterpret_cast<const float4*>(src + c*VP + v0);
            float4 a5 = *reinterpret_cast<const float4*>(src + c*VP + v0 + 4);
            float4 b4 = *reinterpret_cast<const float4*>(wsel + c*64 + d0);
            acc[0][0] += b4.x*a4.x; acc[0][1] += b4.x*a4.y; acc[0][2] += b4.x*a4.z; acc[0][3] += b4.x*a4.w;
            acc[0][4] += b4.x*a5.x; acc[0][5] += b4.x*a5.y; acc[0][6] += b4.x*a5.z; acc[0][7] += b4.x*a5.w;
            acc[1][0] += b4.y*a4.x; acc[1][1] += b4.y*a4.y; acc[1][2] += b4.y*a4.z; acc[1][3] += b4.y*a4.w;
            acc[1][4] += b4.y*a5.x; acc[1][5] += b4.y*a5.y; acc[1][6] += b4.y*a5.z; acc[1][7] += b4.y*a5.w;
            acc[2][0] += b4.z*a4.x; acc[2][1] += b4.z*a4.y; acc[2][2] += b4.z*a4.z; acc[2][3] += b4.z*a4.w;
            acc[2][4] += b4.z*a5.x; acc[2][5] += b4.z*a5.y; acc[2][6] += b4.z*a5.z; acc[2][7] += b4.z*a5.w;
            acc[3][0] += b4.w*a4.x; acc[3][1] += b4.w*a4.y; acc[3][2] += b4.w*a4.z; acc[3][3] += b4.w*a4.w;
            acc[3][4] += b4.w*a5.x; acc[3][5] += b4.w*a5.y; acc[3][6] += b4.w*a5.z; acc[3][7] += b4.w*a5.w;
        }
        if (m < 2) {
            float* dst = (m == 0) ? sQT : sKT;
            #pragma unroll
            for (int di = 0; di < 4; di++) {
                float4 o; o.x = acc[di][0]; o.y = acc[di][1]; o.z = acc[di][2]; o.w = acc[di][3];
                *reinterpret_cast<float4*>(dst + (d0+di)*VP + v0) = o;
                if (vg8 < 3) {
                    float4 o2; o2.x = acc[di][4]; o2.y = acc[di][5]; o2.z = acc[di][6]; o2.w = acc[di][7];
                    *reinterpret_cast<float4*>(dst + (d0+di)*VP + v0 + 4) = o2;
                }
            }
        } else {
            #pragma unroll
            for (int vi = 0; vi < 8; vi++) {
                if (v0 + vi < 25) {
                    #pragma unroll
                    for (int di = 0; di < 4; di++)
                        sVB[(v0+vi)*VB_S + d0 + di] = acc[di][vi];
                }
            }
        }
    }
    __syncthreads();

    // ---------------- S4: scores scT[h][w][vq] = (q.k)/4 (196 thr) -----------
    if (tid < 196) {
        int h = tid / 49, rr = tid % 49;
        int wg = rr % 7, vqg = rr / 7;
        int w0 = wg * 4, vq0 = vqg * 4;
        const float* qb = sQT + h*16*VP;
        const float* kb = sKT + h*16*VP;
        float acc[4][4];
        #pragma unroll
        for (int i = 0; i < 4; i++)
            #pragma unroll
            for (int j = 0; j < 4; j++) acc[i][j] = 0.f;
        #pragma unroll 4
        for (int d = 0; d < 16; d++) {
            float4 a4 = *reinterpret_cast<const float4*>(qb + d*VP + vq0);
            float4 b4 = *reinterpret_cast<const float4*>(kb + d*VP + w0);
            acc[0][0] += b4.x*a4.x; acc[0][1] += b4.x*a4.y; acc[0][2] += b4.x*a4.z; acc[0][3] += b4.x*a4.w;
            acc[1][0] += b4.y*a4.x; acc[1][1] += b4.y*a4.y; acc[1][2] += b4.y*a4.z; acc[1][3] += b4.y*a4.w;
            acc[2][0] += b4.z*a4.x; acc[2][1] += b4.z*a4.y; acc[2][2] += b4.z*a4.z; acc[2][3] += b4.z*a4.w;
            acc[3][0] += b4.w*a4.x; acc[3][1] += b4.w*a4.y; acc[3][2] += b4.w*a4.z; acc[3][3] += b4.w*a4.w;
        }
        float* scb = sSC + h*784;
        #pragma unroll
        for (int wi = 0; wi < 4; wi++) {
            float4 o; o.x = acc[wi][0]*0.25f; o.y = acc[wi][1]*0.25f;
            o.z = acc[wi][2]*0.25f; o.w = acc[wi][3]*0.25f;
            *reinterpret_cast<float4*>(scb + (w0+wi)*VP + vq0) = o;
        }
    }
    __syncthreads();

    // ---------------- S5: softmax over w (parallel, 4 lanes per column) ------
    if (tid < 400) {
        int col = tid >> 2, sub = tid & 3;
        int h = col / 25, vq = col % 25;
        float* base = sSC + h*784 + vq;
        unsigned gm = 0xFu << ((tid & 31) & ~3);
        float mx = -1e30f;
        for (int w = sub; w < 25; w += 4) mx = fmaxf(mx, base[w*VP]);
        mx = fmaxf(mx, __shfl_xor_sync(gm, mx, 1));
        mx = fmaxf(mx, __shfl_xor_sync(gm, mx, 2));
        float s = 0.f;
        for (int w = sub; w < 25; w += 4) s += __expf(base[w*VP] - mx);
        s += __shfl_xor_sync(gm, s, 1);
        s += __shfl_xor_sync(gm, s, 2);
        float inv = 1.f / s;
        for (int w = sub; w < 25; w += 4) base[w*VP] = __expf(base[w*VP] - mx) * inv;
    }
    __syncthreads();

    // ---------------- S6: xoT[e][v] = sum_w attn[h][w][v] * vB[w][e] ----------
    if (tid < 112) {
        int vg = tid % 7, eg = tid / 7;
        int v0 = vg * 4, e0 = eg * 4;
        int h = eg >> 2;
        const float* scb = sSC + h*784;
        float acc[4][4];
        #pragma unroll
        for (int i = 0; i < 4; i++)
            #pragma unroll
            for (int j = 0; j < 4; j++) acc[i][j] = 0.f;
        #pragma unroll 5
        for (int w = 0; w < 25; w++) {
            float4 a4 = *reinterpret_cast<const float4*>(sVB + w*VB_S + e0);
            float4 b4 = *reinterpret_cast<const float4*>(scb + w*VP + v0);
            acc[0][0] += a4.x*b4.x; acc[0][1] += a4.x*b4.y; acc[0][2] += a4.x*b4.z; acc[0][3] += a4.x*b4.w;
            acc[1][0] += a4.y*b4.x; acc[1][1] += a4.y*b4.y; acc[1][2] += a4.y*b4.z; acc[1][3] += a4.y*b4.w;
            acc[2][0] += a4.z*b4.x; acc[2][1] += a4.z*b4.y; acc[2][2] += a4.z*b4.z; acc[2][3] += a4.z*b4.w;
            acc[3][0] += a4.w*b4.x; acc[3][1] += a4.w*b4.y; acc[3][2] += a4.w*b4.z; acc[3][3] += a4.w*b4.w;
        }
        #pragma unroll
        for (int ei = 0; ei < 4; ei++) {
            float4 o; o.x = acc[ei][0]; o.y = acc[ei][1]; o.z = acc[ei][2]; o.w = acc[ei][3];
            *reinterpret_cast<float4*>(sXOT + (e0+ei)*VP + v0) = o;
        }
    }
    __syncthreads();

    // ---------------- S7: P5 fa2 (112 thr) || conv (192 thr, 8v tiles) -------
    if (tid < 112) {
        int vg = tid % 7, cg = tid / 7;
        int v0 = vg * 4, c0 = cg * 4;
        float acc[4][4];
        #pragma unroll
        for (int vi = 0; vi < 4; vi++)
            #pragma unroll
            for (int ci = 0; ci < 4; ci++)
                acc[vi][ci] = sFAT[(c0+ci)*VP + v0 + vi];   // residual
        #pragma unroll 4
        for (int e = 0; e < 64; e++) {
            float4 a4 = *reinterpret_cast<const float4*>(sXOT + e*VP + v0);
            float4 b4 = *reinterpret_cast<const float4*>(fcw + e*64 + c0);
            acc[0][0] += a4.x*b4.x; acc[0][1] += a4.x*b4.y; acc[0][2] += a4.x*b4.z; acc[0][3] += a4.x*b4.w;
            acc[1][0] += a4.y*b4.x; acc[1][1] += a4.y*b4.y; acc[1][2] += a4.y*b4.z; acc[1][3] += a4.y*b4.w;
            acc[2][0] += a4.z*b4.x; acc[2][1] += a4.z*b4.y; acc[2][2] += a4.z*b4.z; acc[2][3] += a4.z*b4.w;
            acc[3][0] += a4.w*b4.x; acc[3][1] += a4.w*b4.y; acc[3][2] += a4.w*b4.z; acc[3][3] += a4.w*b4.w;
        }
        #pragma unroll
        for (int vi = 0; vi < 4; vi++) {
            if (v0 + vi < 25) {
                float4 o; o.x = acc[vi][0]; o.y = acc[vi][1]; o.z = acc[vi][2]; o.w = acc[vi][3];
                *reinterpret_cast<float4*>(sFA2 + (v0+vi)*VB_S + c0) = o;
            }
        }
    } else if (tid < 304) {
        conv_tile8(tid - 112, sFAT, convw, convb, sG);
    }
    __syncthreads();

    // ---------------- S8: f_c = g x A, combine, bn2, relu, store -------------
    if (tid < 112) {
        int wg = tid % 7, cog = tid / 7;
        int w0 = wg * 4, co0 = cog * 4;
        float gate = sGate[0];
        float acc[4][4];
        #pragma unroll
        for (int i = 0; i < 4; i++)
            #pragma unroll
            for (int j = 0; j < 4; j++) acc[i][j] = 0.f;
        #pragma unroll 5
        for (int kv = 0; kv < 75; kv++) {
            float4 a4 = *reinterpret_cast<const float4*>(sA + kv*VP + w0);
            float4 b4 = *reinterpret_cast<const float4*>(sG + kv*64 + co0);
            acc[0][0] += a4.x*b4.x; acc[0][1] += a4.x*b4.y; acc[0][2] += a4.x*b4.z; acc[0][3] += a4.x*b4.w;
            acc[1][0] += a4.y*b4.x; acc[1][1] += a4.y*b4.y; acc[1][2] += a4.y*b4.z; acc[1][3] += a4.y*b4.w;
            acc[2][0] += a4.z*b4.x; acc[2][1] += a4.z*b4.y; acc[2][2] += a4.z*b4.z; acc[2][3] += a4.z*b4.w;
            acc[3][0] += a4.w*b4.x; acc[3][1] += a4.w*b4.y; acc[3][2] += a4.w*b4.z; acc[3][3] += a4.w*b4.w;
        }
        #pragma unroll
        for (int coi = 0; coi < 4; coi++) {
            int co = co0 + coi;
            float s2 = sB2S[co], b2 = sB2B[co];
            float* ob = out + ((size_t)(n*64 + co))*7500 + t*25;
            #pragma unroll
            for (int wi = 0; wi < 4; wi++) {
                int w = w0 + wi;
                if (w < 25) {
                    float f = (sFA2[w*VB_S + co] * gate + acc[wi][coi]) * 0.5f;
                    ob[w] = fmaxf(f * s2 + b2, 0.f);
                }
            }
        }
    }
}

extern "C" void kernel_launch(void* const* d_in, const int* in_sizes, int n_in,
                              void* d_out, int out_size) {
    const float* x     = (const float*)d_in[0];
    const float* Ag    = (const float*)d_in[1];
    const float* bn1g  = (const float*)d_in[2];
    const float* bn1b  = (const float*)d_in[3];
    const float* bn1m  = (const float*)d_in[4];
    const float* bn1v  = (const float*)d_in[5];
    const float* convw = (const float*)d_in[6];
    const float* convb = (const float*)d_in[7];
    const float* lng   = (const float*)d_in[8];
    const float* lnb   = (const float*)d_in[9];
    const float* wq    = (const float*)d_in[10];
    const float* wk    = (const float*)d_in[11];
    const float* wv    = (const float*)d_in[12];
    const float* fcw   = (const float*)d_in[13];
    const float* gatep = (const float*)d_in[14];
    const float* bn2g  = (const float*)d_in[15];
    const float* bn2b  = (const float*)d_in[16];
    const float* bn2m  = (const float*)d_in[17];
    const float* bn2v  = (const float*)d_in[18];
    float* outp = (float*)d_out;

    (void)cudaFuncSetAttribute(intentgcn_kernel,
                               cudaFuncAttributeMaxDynamicSharedMemorySize, SMEM_BYTES);
    dim3 grid(300, 32);
    intentgcn_kernel<<<grid, 512, SMEM_BYTES>>>(
        x, Ag, bn1g, bn1b, bn1m, bn1v, convw, convb, lng, lnb,
        wq, wk, wv, fcw, gatep, bn2g, bn2b, bn2m, bn2v, outp);
}

// round 12
// speedup vs baseline: 1.4043x; 1.0376x over previous
#include <cuda_runtime.h>

// IntentGCN fused kernel v7: v6 + 8-wide-v tiles in S4 (scores), S7 (fa2), S8 (merge).
// N=32, C_IN=C_OUT=64, K=3, T=300, V=25, H=4, DK=DV=16.

#define VP 28    // padded v (stride for [*][v] arrays)
#define VB_S 68  // stride for [v][64] and fa2 arrays

// shared memory float offsets (v2 map)
#define OF_FAT  0        // faT[64][28]
#define OF_QNT  1792     // qnT[64][28]
#define OF_QT   3584     // qT[64][28]
#define OF_KT   5376     // kT[64][28]
#define OF_VB   7168     // vB[25][68]
#define OF_SC   8868     // scT[4][28][28]
#define OF_XOT  12004    // xoT[64][28]
#define OF_FA2  13796    // fa2[25][68]
#define OF_G    15496    // g[75][64]
#define OF_A    20296    // A[75][28]
#define OF_MISC 22396
#define SMEM_FLOATS 22852
#define SMEM_BYTES (SMEM_FLOATS * 4)

// Conv tile, 4co x 8v (ct in 0..191): g[k][v0..v0+7][co0..co0+3] = fa @ conv_w[k]^T + bias
__device__ __forceinline__ void conv_tile8(int ct, const float* __restrict__ sFAT,
                                           const float* __restrict__ convw,
                                           const float* __restrict__ convb,
                                           float* __restrict__ sG)
{
    int k = ct / 64, rr = ct % 64;
    int cog = rr >> 2, vg8 = rr & 3;
    int co0 = cog * 4, v0 = vg8 * 8;
    const float* wb = convw + (k*64 + co0) * 64;
    float acc[8][4];                     // [vi][coi]
    #pragma unroll
    for (int coi = 0; coi < 4; coi++) {
        float bv = convb[k*64 + co0 + coi];
        #pragma unroll
        for (int vi = 0; vi < 8; vi++) acc[vi][coi] = bv;
    }
    #pragma unroll 2
    for (int ci0 = 0; ci0 < 64; ci0 += 4) {
        float4 rb0 = *reinterpret_cast<const float4*>(wb + 0*64 + ci0);
        float4 rb1 = *reinterpret_cast<const float4*>(wb + 1*64 + ci0);
        float4 rb2 = *reinterpret_cast<const float4*>(wb + 2*64 + ci0);
        float4 rb3 = *reinterpret_cast<const float4*>(wb + 3*64 + ci0);
        #pragma unroll
        for (int j = 0; j < 4; j++) {
            float4 la = *reinterpret_cast<const float4*>(sFAT + (ci0+j)*VP + v0);
            float4 lb = *reinterpret_cast<const float4*>(sFAT + (ci0+j)*VP + v0 + 4);
            float w0v = (j==0)?rb0.x:((j==1)?rb0.y:((j==2)?rb0.z:rb0.w));
            float w1v = (j==0)?rb1.x:((j==1)?rb1.y:((j==2)?rb1.z:rb1.w));
            float w2v = (j==0)?rb2.x:((j==1)?rb2.y:((j==2)?rb2.z:rb2.w));
            float w3v = (j==0)?rb3.x:((j==1)?rb3.y:((j==2)?rb3.z:rb3.w));
            acc[0][0] += la.x*w0v; acc[0][1] += la.x*w1v; acc[0][2] += la.x*w2v; acc[0][3] += la.x*w3v;
            acc[1][0] += la.y*w0v; acc[1][1] += la.y*w1v; acc[1][2] += la.y*w2v; acc[1][3] += la.y*w3v;
            acc[2][0] += la.z*w0v; acc[2][1] += la.z*w1v; acc[2][2] += la.z*w2v; acc[2][3] += la.z*w3v;
            acc[3][0] += la.w*w0v; acc[3][1] += la.w*w1v; acc[3][2] += la.w*w2v; acc[3][3] += la.w*w3v;
            acc[4][0] += lb.x*w0v; acc[4][1] += lb.x*w1v; acc[4][2] += lb.x*w2v; acc[4][3] += lb.x*w3v;
            acc[5][0] += lb.y*w0v; acc[5][1] += lb.y*w1v; acc[5][2] += lb.y*w2v; acc[5][3] += lb.y*w3v;
            acc[6][0] += lb.z*w0v; acc[6][1] += lb.z*w1v; acc[6][2] += lb.z*w2v; acc[6][3] += lb.z*w3v;
            acc[7][0] += lb.w*w0v; acc[7][1] += lb.w*w1v; acc[7][2] += lb.w*w2v; acc[7][3] += lb.w*w3v;
        }
    }
    #pragma unroll
    for (int vi = 0; vi < 8; vi++) {
        if (v0 + vi < 25) {
            float4 o; o.x = acc[vi][0]; o.y = acc[vi][1]; o.z = acc[vi][2]; o.w = acc[vi][3];
            *reinterpret_cast<float4*>(sG + (k*25 + v0 + vi)*64 + co0) = o;
        }
    }
}

__global__ __launch_bounds__(512, 2)
void intentgcn_kernel(
    const float* __restrict__ x,    const float* __restrict__ Ag,
    const float* __restrict__ bn1g, const float* __restrict__ bn1b,
    const float* __restrict__ bn1m, const float* __restrict__ bn1v,
    const float* __restrict__ convw, const float* __restrict__ convb,
    const float* __restrict__ lng,  const float* __restrict__ lnb,
    const float* __restrict__ wq,   const float* __restrict__ wk,
    const float* __restrict__ wv,   const float* __restrict__ fcw,
    const float* __restrict__ gatep,
    const float* __restrict__ bn2g, const float* __restrict__ bn2b,
    const float* __restrict__ bn2m, const float* __restrict__ bn2v,
    float* __restrict__ out)
{
    extern __shared__ float sm[];
    float* sFAT = sm + OF_FAT;
    float* sQNT = sm + OF_QNT;
    float* sQT  = sm + OF_QT;
    float* sKT  = sm + OF_KT;
    float* sVB  = sm + OF_VB;
    float* sSC  = sm + OF_SC;
    float* sXOT = sm + OF_XOT;
    float* sFA2 = sm + OF_FA2;
    float* sG   = sm + OF_G;
    float* sA   = sm + OF_A;
    float* sB1S = sm + OF_MISC;
    float* sB1B = sB1S + 64;
    float* sB2S = sB1B + 64;
    float* sB2B = sB2S + 64;
    float* sLNg = sB2B + 64;
    float* sLNb = sLNg + 64;
    float* sMU  = sLNb + 64;   // 32
    float* sRS  = sMU + 32;    // 32
    float* sGate = sRS + 32;

    const int tid = threadIdx.x;
    const int t = blockIdx.x;
    const int n = blockIdx.y;

    // ---------------- S0: params, A, pad-zeroing, bn1 ----------------
    if (tid < 64) {
        float s1 = bn1g[tid] * rsqrtf(bn1v[tid] + 1e-5f);
        sB1S[tid] = s1;
        sB1B[tid] = bn1b[tid] - bn1m[tid] * s1;
        float s2 = bn2g[tid] * rsqrtf(bn2v[tid] + 1e-5f);
        sB2S[tid] = s2;
        sB2B[tid] = bn2b[tid] - bn2m[tid] * s2;
        sLNg[tid] = lng[tid];
        sLNb[tid] = lnb[tid];
    }
    if (tid == 0) sGate[0] = gatep[0];
    for (int i = tid; i < 192; i += 512) {           // zero padded v-cols
        int c = i / 3, vp = 25 + i % 3;
        sFAT[c*VP + vp] = 0.f;
        sQNT[c*VP + vp] = 0.f;
    }
    for (int i = tid; i < 225; i += 512)             // zero padded A w-cols
        sA[(i/3)*VP + 25 + i % 3] = 0.f;
    for (int i = tid; i < 1875; i += 512) {          // A[75][25] -> stride 28
        int kv = i / 25, w = i - kv*25;
        sA[kv*VP + w] = Ag[i];
    }
    __syncthreads();

    const float* xb = x + (size_t)(n*64*300 + t) * 25;
    for (int i = tid; i < 1600; i += 512) {
        int c = i / 25, v = i - c*25;
        sFAT[c*VP + v] = xb[c*7500 + v] * sB1S[c] + sB1B[c];
    }
    __syncthreads();

    // ---------------- S1: per-token LayerNorm stats (parallel shfl tree) -----
    if (tid < 256) {
        int v = tid >> 3;
        int j = tid & 7;
        int vv = (v < 25) ? v : 24;
        float s = 0.f, s2 = 0.f;
        #pragma unroll
        for (int cc = 0; cc < 8; cc++) {
            float xv = sFAT[(j*8 + cc)*VP + vv];
            s += xv; s2 += xv*xv;
        }
        s  += __shfl_down_sync(0xFFFFFFFFu, s, 4);
        s2 += __shfl_down_sync(0xFFFFFFFFu, s2, 4);
        s  += __shfl_down_sync(0xFFFFFFFFu, s, 2);
        s2 += __shfl_down_sync(0xFFFFFFFFu, s2, 2);
        s  += __shfl_down_sync(0xFFFFFFFFu, s, 1);
        s2 += __shfl_down_sync(0xFFFFFFFFu, s2, 1);
        if (j == 0 && v < 25) {
            float mu = s * (1.f/64.f);
            float var = s2 * (1.f/64.f) - mu*mu;
            sMU[v] = mu;
            sRS[v] = rsqrtf(var + 1e-6f);
        }
    }
    __syncthreads();

    // ---------------- S2: qn (float4) ----------------
    if (tid < 448) {
        int c = tid / 7, j = tid % 7;
        float lg = sLNg[c], lb = sLNb[c];
        if (j < 6) {
            int v0 = j * 4;
            float4 f4 = *reinterpret_cast<const float4*>(sFAT + c*VP + v0);
            float4 m4 = *reinterpret_cast<const float4*>(sMU + v0);
            float4 r4 = *reinterpret_cast<const float4*>(sRS + v0);
            float4 o;
            o.x = (f4.x - m4.x) * r4.x * lg + lb;
            o.y = (f4.y - m4.y) * r4.y * lg + lb;
            o.z = (f4.z - m4.z) * r4.z * lg + lb;
            o.w = (f4.w - m4.w) * r4.w * lg + lb;
            *reinterpret_cast<float4*>(sQNT + c*VP + v0) = o;
        } else {
            sQNT[c*VP + 24] = (sFAT[c*VP + 24] - sMU[24]) * sRS[24] * lg + lb;
        }
    }
    __syncthreads();

    // ---------------- S3: q/k/v projections (192 thr, 4d x 8v tiles) ---------
    if (tid < 192) {
        int m = tid >> 6, r = tid & 63;
        int vg8 = r & 3, dg = r >> 2;
        int v0 = vg8 * 8, d0 = dg * 4;
        const float* src = (m == 0) ? sQNT : sFAT;
        const float* wsel = (m == 0) ? wq : ((m == 1) ? wk : wv);
        float acc[4][8];                 // [di][vi]
        #pragma unroll
        for (int i = 0; i < 4; i++)
            #pragma unroll
            for (int j = 0; j < 8; j++) acc[i][j] = 0.f;
        #pragma unroll 4
        for (int c = 0; c < 64; c++) {
            float4 a4 = *reinterpret_cast<const float4*>(src + c*VP + v0);
            float4 a5 = *reinterpret_cast<const float4*>(src + c*VP + v0 + 4);
            float4 b4 = *reinterpret_cast<const float4*>(wsel + c*64 + d0);
            acc[0][0] += b4.x*a4.x; acc[0][1] += b4.x*a4.y; acc[0][2] += b4.x*a4.z; acc[0][3] += b4.x*a4.w;
            acc[0][4] += b4.x*a5.x; acc[0][5] += b4.x*a5.y; acc[0][6] += b4.x*a5.z; acc[0][7] += b4.x*a5.w;
            acc[1][0] += b4.y*a4.x; acc[1][1] += b4.y*a4.y; acc[1][2] += b4.y*a4.z; acc[1][3] += b4.y*a4.w;
            acc[1][4] += b4.y*a5.x; acc[1][5] += b4.y*a5.y; acc[1][6] += b4.y*a5.z; acc[1][7] += b4.y*a5.w;
            acc[2][0] += b4.z*a4.x; acc[2][1] += b4.z*a4.y; acc[2][2] += b4.z*a4.z; acc[2][3] += b4.z*a4.w;
            acc[2][4] += b4.z*a5.x; acc[2][5] += b4.z*a5.y; acc[2][6] += b4.z*a5.z; acc[2][7] += b4.z*a5.w;
            acc[3][0] += b4.w*a4.x; acc[3][1] += b4.w*a4.y; acc[3][2] += b4.w*a4.z; acc[3][3] += b4.w*a4.w;
            acc[3][4] += b4.w*a5.x; acc[3][5] += b4.w*a5.y; acc[3][6] += b4.w*a5.z; acc[3][7] += b4.w*a5.w;
        }
        if (m < 2) {
            float* dst = (m == 0) ? sQT : sKT;
            #pragma unroll
            for (int di = 0; di < 4; di++) {
                float4 o; o.x = acc[di][0]; o.y = acc[di][1]; o.z = acc[di][2]; o.w = acc[di][3];
                *reinterpret_cast<float4*>(dst + (d0+di)*VP + v0) = o;
                if (vg8 < 3) {
                    float4 o2; o2.x = acc[di][4]; o2.y = acc[di][5]; o2.z = acc[di][6]; o2.w = acc[di][7];
                    *reinterpret_cast<float4*>(dst + (d0+di)*VP + v0 + 4) = o2;
                }
            }
        } else {
            #pragma unroll
            for (int vi = 0; vi < 8; vi++) {
                if (v0 + vi < 25) {
                    #pragma unroll
                    for (int di = 0; di < 4; di++)
                        sVB[(v0+vi)*VB_S + d0 + di] = acc[di][vi];
                }
            }
        }
    }
    __syncthreads();

    // ---------------- S4: scores (112 thr, 4w x 8vq tiles) -------------------
    if (tid < 112) {
        int h = tid / 28, rr = tid % 28;
        int wg = rr % 7, vqg = rr / 7;       // vqg 0..3
        int w0 = wg * 4, vq0 = vqg * 8;
        const float* qb = sQT + h*16*VP;
        const float* kb = sKT + h*16*VP;
        float acc[4][8];                     // [wi][vqi]
        #pragma unroll
        for (int i = 0; i < 4; i++)
            #pragma unroll
            for (int j = 0; j < 8; j++) acc[i][j] = 0.f;
        #pragma unroll 4
        for (int d = 0; d < 16; d++) {
            float4 a4 = *reinterpret_cast<const float4*>(qb + d*VP + vq0);
            float4 a5 = *reinterpret_cast<const float4*>(qb + d*VP + vq0 + 4);
            float4 b4 = *reinterpret_cast<const float4*>(kb + d*VP + w0);
            acc[0][0] += b4.x*a4.x; acc[0][1] += b4.x*a4.y; acc[0][2] += b4.x*a4.z; acc[0][3] += b4.x*a4.w;
            acc[0][4] += b4.x*a5.x; acc[0][5] += b4.x*a5.y; acc[0][6] += b4.x*a5.z; acc[0][7] += b4.x*a5.w;
            acc[1][0] += b4.y*a4.x; acc[1][1] += b4.y*a4.y; acc[1][2] += b4.y*a4.z; acc[1][3] += b4.y*a4.w;
            acc[1][4] += b4.y*a5.x; acc[1][5] += b4.y*a5.y; acc[1][6] += b4.y*a5.z; acc[1][7] += b4.y*a5.w;
            acc[2][0] += b4.z*a4.x; acc[2][1] += b4.z*a4.y; acc[2][2] += b4.z*a4.z; acc[2][3] += b4.z*a4.w;
            acc[2][4] += b4.z*a5.x; acc[2][5] += b4.z*a5.y; acc[2][6] += b4.z*a5.z; acc[2][7] += b4.z*a5.w;
            acc[3][0] += b4.w*a4.x; acc[3][1] += b4.w*a4.y; acc[3][2] += b4.w*a4.z; acc[3][3] += b4.w*a4.w;
            acc[3][4] += b4.w*a5.x; acc[3][5] += b4.w*a5.y; acc[3][6] += b4.w*a5.z; acc[3][7] += b4.w*a5.w;
        }
        float* scb = sSC + h*784;
        #pragma unroll
        for (int wi = 0; wi < 4; wi++) {
            float4 o; o.x = acc[wi][0]*0.25f; o.y = acc[wi][1]*0.25f;
            o.z = acc[wi][2]*0.25f; o.w = acc[wi][3]*0.25f;
            *reinterpret_cast<float4*>(scb + (w0+wi)*VP + vq0) = o;
            if (vqg < 3) {   // second float4 would cross the row at vq0=24
                float4 o2; o2.x = acc[wi][4]*0.25f; o2.y = acc[wi][5]*0.25f;
                o2.z = acc[wi][6]*0.25f; o2.w = acc[wi][7]*0.25f;
                *reinterpret_cast<float4*>(scb + (w0+wi)*VP + vq0 + 4) = o2;
            }
        }
    }
    __syncthreads();

    // ---------------- S5: softmax over w (parallel, 4 lanes per column) ------
    if (tid < 400) {
        int col = tid >> 2, sub = tid & 3;
        int h = col / 25, vq = col % 25;
        float* base = sSC + h*784 + vq;
        unsigned gm = 0xFu << ((tid & 31) & ~3);
        float mx = -1e30f;
        for (int w = sub; w < 25; w += 4) mx = fmaxf(mx, base[w*VP]);
        mx = fmaxf(mx, __shfl_xor_sync(gm, mx, 1));
        mx = fmaxf(mx, __shfl_xor_sync(gm, mx, 2));
        float s = 0.f;
        for (int w = sub; w < 25; w += 4) s += __expf(base[w*VP] - mx);
        s += __shfl_xor_sync(gm, s, 1);
        s += __shfl_xor_sync(gm, s, 2);
        float inv = 1.f / s;
        for (int w = sub; w < 25; w += 4) base[w*VP] = __expf(base[w*VP] - mx) * inv;
    }
    __syncthreads();

    // ---------------- S6: xoT[e][v] = sum_w attn[h][w][v] * vB[w][e] ----------
    if (tid < 112) {
        int vg = tid % 7, eg = tid / 7;
        int v0 = vg * 4, e0 = eg * 4;
        int h = eg >> 2;
        const float* scb = sSC + h*784;
        float acc[4][4];
        #pragma unroll
        for (int i = 0; i < 4; i++)
            #pragma unroll
            for (int j = 0; j < 4; j++) acc[i][j] = 0.f;
        #pragma unroll 5
        for (int w = 0; w < 25; w++) {
            float4 a4 = *reinterpret_cast<const float4*>(sVB + w*VB_S + e0);
            float4 b4 = *reinterpret_cast<const float4*>(scb + w*VP + v0);
            acc[0][0] += a4.x*b4.x; acc[0][1] += a4.x*b4.y; acc[0][2] += a4.x*b4.z; acc[0][3] += a4.x*b4.w;
            acc[1][0] += a4.y*b4.x; acc[1][1] += a4.y*b4.y; acc[1][2] += a4.y*b4.z; acc[1][3] += a4.y*b4.w;
            acc[2][0] += a4.z*b4.x; acc[2][1] += a4.z*b4.y; acc[2][2] += a4.z*b4.z; acc[2][3] += a4.z*b4.w;
            acc[3][0] += a4.w*b4.x; acc[3][1] += a4.w*b4.y; acc[3][2] += a4.w*b4.z; acc[3][3] += a4.w*b4.w;
        }
        #pragma unroll
        for (int ei = 0; ei < 4; ei++) {
            float4 o; o.x = acc[ei][0]; o.y = acc[ei][1]; o.z = acc[ei][2]; o.w = acc[ei][3];
            *reinterpret_cast<float4*>(sXOT + (e0+ei)*VP + v0) = o;
        }
    }
    __syncthreads();

    // ---------------- S7: fa2 (64 thr, 4c x 8v) || conv (192 thr, 8v) --------
    if (tid < 64) {
        int cg = tid >> 2, vg8 = tid & 3;
        int c0 = cg * 4, v0 = vg8 * 8;
        float acc[8][4];                     // [vi][ci]
        #pragma unroll
        for (int vi = 0; vi < 8; vi++)
            #pragma unroll
            for (int ci = 0; ci < 4; ci++)
                acc[vi][ci] = sFAT[(c0+ci)*VP + v0 + vi];   // residual (overreads discarded)
        #pragma unroll 4
        for (int e = 0; e < 64; e++) {
            float4 a4 = *reinterpret_cast<const float4*>(sXOT + e*VP + v0);
            float4 a5 = *reinterpret_cast<const float4*>(sXOT + e*VP + v0 + 4);
            float4 b4 = *reinterpret_cast<const float4*>(fcw + e*64 + c0);
            acc[0][0] += a4.x*b4.x; acc[0][1] += a4.x*b4.y; acc[0][2] += a4.x*b4.z; acc[0][3] += a4.x*b4.w;
            acc[1][0] += a4.y*b4.x; acc[1][1] += a4.y*b4.y; acc[1][2] += a4.y*b4.z; acc[1][3] += a4.y*b4.w;
            acc[2][0] += a4.z*b4.x; acc[2][1] += a4.z*b4.y; acc[2][2] += a4.z*b4.z; acc[2][3] += a4.z*b4.w;
            acc[3][0] += a4.w*b4.x; acc[3][1] += a4.w*b4.y; acc[3][2] += a4.w*b4.z; acc[3][3] += a4.w*b4.w;
            acc[4][0] += a5.x*b4.x; acc[4][1] += a5.x*b4.y; acc[4][2] += a5.x*b4.z; acc[4][3] += a5.x*b4.w;
            acc[5][0] += a5.y*b4.x; acc[5][1] += a5.y*b4.y; acc[5][2] += a5.y*b4.z; acc[5][3] += a5.y*b4.w;
            acc[6][0] += a5.z*b4.x; acc[6][1] += a5.z*b4.y; acc[6][2] += a5.z*b4.z; acc[6][3] += a5.z*b4.w;
            acc[7][0] += a5.w*b4.x; acc[7][1] += a5.w*b4.y; acc[7][2] += a5.w*b4.z; acc[7][3] += a5.w*b4.w;
        }
        #pragma unroll
        for (int vi = 0; vi < 8; vi++) {
            if (v0 + vi < 25) {
                float4 o; o.x = acc[vi][0]; o.y = acc[vi][1]; o.z = acc[vi][2]; o.w = acc[vi][3];
                *reinterpret_cast<float4*>(sFA2 + (v0+vi)*VB_S + c0) = o;
            }
        }
    } else if (tid < 256) {
        conv_tile8(tid - 64, sFAT, convw, convb, sG);
    }
    __syncthreads();

    // ---------------- S8: merge (64 thr, 4co x 8w) ---------------------------
    if (tid < 64) {
        int cog = tid >> 2, wg8 = tid & 3;
        int co0 = cog * 4, w0 = wg8 * 8;
        float gate = sGate[0];
        float acc[8][4];                     // [wi][coi]
        #pragma unroll
        for (int i = 0; i < 8; i++)
            #pragma unroll
            for (int j = 0; j < 4; j++) acc[i][j] = 0.f;
        #pragma unroll 5
        for (int kv = 0; kv < 75; kv++) {
            float4 a4 = *reinterpret_cast<const float4*>(sA + kv*VP + w0);
            float4 a5 = *reinterpret_cast<const float4*>(sA + kv*VP + w0 + 4);
            float4 b4 = *reinterpret_cast<const float4*>(sG + kv*64 + co0);
            acc[0][0] += a4.x*b4.x; acc[0][1] += a4.x*b4.y; acc[0][2] += a4.x*b4.z; acc[0][3] += a4.x*b4.w;
            acc[1][0] += a4.y*b4.x; acc[1][1] += a4.y*b4.y; acc[1][2] += a4.y*b4.z; acc[1][3] += a4.y*b4.w;
            acc[2][0] += a4.z*b4.x; acc[2][1] += a4.z*b4.y; acc[2][2] += a4.z*b4.z; acc[2][3] += a4.z*b4.w;
            acc[3][0] += a4.w*b4.x; acc[3][1] += a4.w*b4.y; acc[3][2] += a4.w*b4.z; acc[3][3] += a4.w*b4.w;
            acc[4][0] += a5.x*b4.x; acc[4][1] += a5.x*b4.y; acc[4][2] += a5.x*b4.z; acc[4][3] += a5.x*b4.w;
            acc[5][0] += a5.y*b4.x; acc[5][1] += a5.y*b4.y; acc[5][2] += a5.y*b4.z; acc[5][3] += a5.y*b4.w;
            acc[6][0] += a5.z*b4.x; acc[6][1] += a5.z*b4.y; acc[6][2] += a5.z*b4.z; acc[6][3] += a5.z*b4.w;
            acc[7][0] += a5.w*b4.x; acc[7][1] += a5.w*b4.y; acc[7][2] += a5.w*b4.z; acc[7][3] += a5.w*b4.w;
        }
        #pragma unroll
        for (int coi = 0; coi < 4; coi++) {
            int co = co0 + coi;
            float s2 = sB2S[co], b2 = sB2B[co];
            float* ob = out + ((size_t)(n*64 + co))*7500 + t*25;
            #pragma unroll
            for (int wi = 0; wi < 8; wi++) {
                int w = w0 + wi;
                if (w < 25) {
                    float f = (sFA2[w*VB_S + co] * gate + acc[wi][coi]) * 0.5f;
                    ob[w] = fmaxf(f * s2 + b2, 0.f);
                }
            }
        }
    }
}

extern "C" void kernel_launch(void* const* d_in, const int* in_sizes, int n_in,
                              void* d_out, int out_size) {
    const float* x     = (const float*)d_in[0];
    const float* Ag    = (const float*)d_in[1];
    const float* bn1g  = (const float*)d_in[2];
    const float* bn1b  = (const float*)d_in[3];
    const float* bn1m  = (const float*)d_in[4];
    const float* bn1v  = (const float*)d_in[5];
    const float* convw = (const float*)d_in[6];
    const float* convb = (const float*)d_in[7];
    const float* lng   = (const float*)d_in[8];
    const float* lnb   = (const float*)d_in[9];
    const float* wq    = (const float*)d_in[10];
    const float* wk    = (const float*)d_in[11];
    const float* wv    = (const float*)d_in[12];
    const float* fcw   = (const float*)d_in[13];
    const float* gatep = (const float*)d_in[14];
    const float* bn2g  = (const float*)d_in[15];
    const float* bn2b  = (const float*)d_in[16];
    const float* bn2m  = (const float*)d_in[17];
    const float* bn2v  = (const float*)d_in[18];
    float* outp = (float*)d_out;

    (void)cudaFuncSetAttribute(intentgcn_kernel,
                               cudaFuncAttributeMaxDynamicSharedMemorySize, SMEM_BYTES);
    dim3 grid(300, 32);
    intentgcn_kernel<<<grid, 512, SMEM_BYTES>>>(
        x, Ag, bn1g, bn1b, bn1m, bn1v, convw, convb, lng, lnb,
        wq, wk, wv, fcw, gatep, bn2g, bn2b, bn2m, bn2v, outp);
}